// round 1
// baseline (speedup 1.0000x reference)
#include <cuda_runtime.h>
#include <cstdint>

// Problem constants (fixed shapes from reference):
// x: [B=8, C=64, H=512, W=512] f32
// W: [O=64, C=64], b: [64], seg_w: [4,4]
// out: [8, 64, 512, 512] f32
// SEG=4, block = 128x128 per segment tile.

#define B_  8
#define C_  64
#define O_  64
#define HW_ 512
#define S_  4
#define BS_ 128            // block side (H/S)
#define PLANE_F4 (HW_*HW_/4)   // 65536 float4 per (b,c) plane
#define BAND_F4  (BS_*HW_/4)   // 16384 float4 per 128-row band
#define ROW_F4   (HW_/4)       // 128 float4 per row

// scratch (allocation-free rule: __device__ globals)
__device__ float g_pooled[B_*C_*S_*S_];    // [b][c][i][j]
__device__ float g_weighted[B_*O_*S_*S_];  // [b][o][i][j]

// ---------------------------------------------------------------------------
// Kernel 1: segment mean pool. One CTA per (b, c, i) band of 128 rows.
// Each thread keeps a fixed column-segment j (loop-invariant since
// (tid + 256k) & 127 == tid & 127), accumulates one partial sum, then
// warp-reduce + tiny shared combine.
// ---------------------------------------------------------------------------
__global__ __launch_bounds__(256) void pool_kernel(const float4* __restrict__ x)
{
    const int bci = blockIdx.x;        // 0 .. B*C*S-1  (2048)
    const int i   = bci & (S_ - 1);
    const int bc  = bci >> 2;          // b*C + c

    const float4* base = x + (size_t)bc * PLANE_F4 + (size_t)i * BAND_F4;

    float acc = 0.0f;
    #pragma unroll 8
    for (int idx = threadIdx.x; idx < BAND_F4; idx += 256) {
        float4 v = base[idx];
        acc += (v.x + v.y) + (v.z + v.w);
    }

    // warp reduce
    #pragma unroll
    for (int off = 16; off > 0; off >>= 1)
        acc += __shfl_xor_sync(0xffffffffu, acc, off);

    // warp w covers column segment j = w & 3 (32 float4 per segment)
    __shared__ float ws[8];
    const int warp = threadIdx.x >> 5;
    if ((threadIdx.x & 31) == 0) ws[warp] = acc;
    __syncthreads();

    if (threadIdx.x < S_) {
        const float inv = 1.0f / (float)(BS_ * BS_);
        float total = ws[threadIdx.x] + ws[threadIdx.x + 4];
        g_pooled[bc * (S_*S_) + i * S_ + threadIdx.x] = total * inv;
    }
}

// ---------------------------------------------------------------------------
// Kernel 2: tiny per-segment linear + bias + seg_w scale.
// 8192 outputs, one thread each, 64 MACs per thread.
// ---------------------------------------------------------------------------
__global__ __launch_bounds__(256) void linear_kernel(const float* __restrict__ Wm,
                                                     const float* __restrict__ bias,
                                                     const float* __restrict__ seg_w)
{
    const int idx = blockIdx.x * 256 + threadIdx.x;   // 0 .. 8191
    if (idx >= B_ * O_ * S_ * S_) return;

    const int ij = idx & 15;
    const int o  = (idx >> 4) & (O_ - 1);
    const int b  = idx >> 10;

    const float* p = g_pooled + b * (C_ * S_ * S_) + ij;
    const float* wrow = Wm + o * C_;

    float acc = bias[o];
    #pragma unroll
    for (int c = 0; c < C_; c++)
        acc = fmaf(p[c * (S_*S_)], wrow[c], acc);

    g_weighted[idx] = acc * seg_w[ij];
}

// ---------------------------------------------------------------------------
// Kernel 3: broadcast each tile value over its 128x128 block.
// One CTA per (b, o, i) band of 128 rows. Each thread's j is loop-invariant,
// so the tile value is selected once and the loop is pure float4 streaming
// stores.
// ---------------------------------------------------------------------------
__global__ __launch_bounds__(256) void bcast_kernel(float4* __restrict__ out)
{
    const int boi = blockIdx.x;        // 0 .. B*O*S-1 (2048)
    const int i   = boi & (S_ - 1);
    const int bo  = boi >> 2;          // b*O + o

    const float* wv = g_weighted + bo * (S_*S_) + i * S_;

    const int j = (threadIdx.x & (ROW_F4 - 1)) >> 5;   // fixed per thread
    const float v = wv[j];
    const float4 f = make_float4(v, v, v, v);

    float4* base = out + (size_t)bo * PLANE_F4 + (size_t)i * BAND_F4;

    #pragma unroll 8
    for (int idx = threadIdx.x; idx < BAND_F4; idx += 256)
        base[idx] = f;
}

// ---------------------------------------------------------------------------
extern "C" void kernel_launch(void* const* d_in, const int* in_sizes, int n_in,
                              void* d_out, int out_size)
{
    const float4* x    = (const float4*)d_in[0];
    const float*  Wm   = (const float*)d_in[1];
    const float*  bias = (const float*)d_in[2];
    const float*  segw = (const float*)d_in[3];
    float4* out = (float4*)d_out;

    pool_kernel<<<B_*C_*S_, 256>>>(x);
    linear_kernel<<<(B_*O_*S_*S_ + 255) / 256, 256>>>(Wm, bias, segw);
    bcast_kernel<<<B_*O_*S_, 256>>>(out);
}